// round 3
// baseline (speedup 1.0000x reference)
#include <cuda_runtime.h>

// Graph TopK pooling: score nodes, exact radix-select threshold, stable
// compaction of kept nodes, gather x, compact edges + attrs.
// All scratch in __device__ globals (no allocs). All kernels graph-capturable.

#define NMAX 100352
#define EMAX 1600000

__device__ float        g_scores[NMAX];
__device__ unsigned int g_hist[65536];
__device__ int          g_prefix;
__device__ int          g_krem;
__device__ unsigned int g_tbits;
__device__ int          g_map[NMAX];
__device__ int          g_poolidx[NMAX / 2 + 256];
__device__ int          g_npart[256];
__device__ int          g_nexcl[256];
__device__ int          g_epart[512];
__device__ int          g_eexcl[512];
__device__ int          g_kept[EMAX];

// ---------------- scores: one warp per node, 128-dim dot ----------------
__global__ void k_scores(const float* __restrict__ x, const float* __restrict__ w,
                         const float* __restrict__ b, int N) {
    int gtid = blockIdx.x * blockDim.x + threadIdx.x;
    int node = gtid >> 5, lane = gtid & 31;
    if (node >= N) return;
    float4 xv = ((const float4*)x)[node * 32 + lane];
    float4 wv = ((const float4*)w)[lane];
    float s = xv.x * wv.x + xv.y * wv.y + xv.z * wv.z + xv.w * wv.w;
#pragma unroll
    for (int o = 16; o > 0; o >>= 1) s += __shfl_down_sync(0xffffffffu, s, o);
    if (lane == 0) {
        float z = s + b[0];
        float sc;
        if (z >= 0.f) sc = 1.f / (1.f + expf(-z));
        else { float e = expf(z); sc = e / (1.f + e); }
        g_scores[node] = sc;
    }
}

__global__ void k_zero_hist() { g_hist[blockIdx.x * 256 + threadIdx.x] = 0u; }

// phase 0: histogram of high 16 bits; phase 1: low 16 bits of elements matching prefix
__global__ void k_hist(int N, int phase) {
    int n = blockIdx.x * blockDim.x + threadIdx.x;
    if (n >= N) return;
    unsigned int bits = __float_as_uint(g_scores[n]);  // scores > 0: bits order = value order
    if (phase == 0) {
        atomicAdd(&g_hist[bits >> 16], 1u);
    } else {
        if ((int)(bits >> 16) == g_prefix) atomicAdd(&g_hist[bits & 0xffffu], 1u);
    }
}

// find bin containing rank k (ascending)
__global__ void k_select(int phase, int k0) {
    __shared__ int ssum[256];
    int t = threadIdx.x;
    int cnt = 0;
    for (int i = 0; i < 256; i++) cnt += (int)g_hist[t * 256 + i];
    ssum[t] = cnt;
    __syncthreads();
    for (int off = 1; off < 256; off <<= 1) {
        int v = (t >= off) ? ssum[t - off] : 0;
        __syncthreads();
        ssum[t] += v;
        __syncthreads();
    }
    int excl = ssum[t] - cnt;
    int k = (phase == 0) ? k0 : g_krem;
    if (k >= excl && k < excl + cnt) {
        int rem = k - excl;
        for (int i = 0; i < 256; i++) {
            int c = (int)g_hist[t * 256 + i];
            if (rem < c) {
                if (phase == 0) { g_prefix = t * 256 + i; g_krem = rem; }
                else            { g_tbits = ((unsigned)g_prefix << 16) | (unsigned)(t * 256 + i); }
                break;
            }
            rem -= c;
        }
    }
}

// ---------------- node compaction: count / scan / write ----------------
__global__ void k_npart(int N) {
    __shared__ int red[256];
    int base = blockIdx.x * 1024;
    unsigned int tb = g_tbits;
    int c = 0;
    for (int i = threadIdx.x; i < 1024; i += 256) {
        int n = base + i;
        if (n < N) c += (__float_as_uint(g_scores[n]) >= tb) ? 1 : 0;
    }
    red[threadIdx.x] = c;
    __syncthreads();
    for (int off = 128; off > 0; off >>= 1) {
        if (threadIdx.x < off) red[threadIdx.x] += red[threadIdx.x + off];
        __syncthreads();
    }
    if (threadIdx.x == 0) g_npart[blockIdx.x] = red[0];
}

__global__ void k_scan_part(int which, int nb) {
    if (threadIdx.x == 0) {
        int run = 0;
        if (which == 0) { for (int i = 0; i < nb; i++) { g_nexcl[i] = run; run += g_npart[i]; } }
        else            { for (int i = 0; i < nb; i++) { g_eexcl[i] = run; run += g_epart[i]; } }
    }
}

__global__ void k_nwrite(int N, int NK, float* __restrict__ out_pool) {
    __shared__ unsigned char sf[1024];
    __shared__ int ssum[256];
    int base = blockIdx.x * 1024;
    unsigned int tb = g_tbits;
    for (int i = threadIdx.x; i < 1024; i += 256) {
        int n = base + i;
        sf[i] = (n < N) ? (unsigned char)(__float_as_uint(g_scores[n]) >= tb) : (unsigned char)0;
    }
    __syncthreads();
    int t = threadIdx.x;
    int loc[4];
    int s = 0;
#pragma unroll
    for (int j = 0; j < 4; j++) { loc[j] = s; s += sf[t * 4 + j]; }
    ssum[t] = s;
    __syncthreads();
    for (int off = 1; off < 256; off <<= 1) {
        int v = (t >= off) ? ssum[t - off] : 0;
        __syncthreads();
        ssum[t] += v;
        __syncthreads();
    }
    int texcl = ssum[t] - s;
    int gb = g_nexcl[blockIdx.x];
#pragma unroll
    for (int j = 0; j < 4; j++) {
        int n = base + t * 4 + j;
        if (n >= N) continue;
        int m = -1;
        if (sf[t * 4 + j]) {
            int r = gb + texcl + loc[j];
            if (r < NK) {  // stable truncation: first NK masked nodes by index
                m = r;
                g_poolidx[r] = n;
                out_pool[r] = (float)n;
            }
        }
        g_map[n] = m;
    }
}

// ---------------- new_x gather: float4 per thread ----------------
__global__ void k_xgather(const float* __restrict__ x, float* __restrict__ outx, int NK) {
    int tid = blockIdx.x * blockDim.x + threadIdx.x;
    if (tid >= NK * 32) return;
    int r = tid >> 5, c = tid & 31;
    int n = g_poolidx[r];
    ((float4*)outx)[tid] = ((const float4*)x)[n * 32 + c];
}

// ---------------- edge compaction: count / scan / write ----------------
__global__ void k_epart(const int* __restrict__ ei, int E) {
    __shared__ int red[256];
    int base = blockIdx.x * 4096;
    int c = 0;
    for (int i = threadIdx.x; i < 4096; i += 256) {
        int e = base + i;
        if (e < E) {
            int s = ei[e], d = ei[E + e];
            c += (g_map[s] >= 0 && g_map[d] >= 0) ? 1 : 0;
        }
    }
    red[threadIdx.x] = c;
    __syncthreads();
    for (int off = 128; off > 0; off >>= 1) {
        if (threadIdx.x < off) red[threadIdx.x] += red[threadIdx.x + off];
        __syncthreads();
    }
    if (threadIdx.x == 0) g_epart[blockIdx.x] = red[0];
}

__global__ void k_ewrite(const int* __restrict__ ei, int E, int Ek,
                         float* __restrict__ out_ei, float* __restrict__ out_eo,
                         float* __restrict__ out_pe) {
    __shared__ unsigned char sf[4096];
    __shared__ int ssum[256];
    int base = blockIdx.x * 4096;
    for (int i = threadIdx.x; i < 4096; i += 256) {
        int e = base + i;
        unsigned char f = 0;
        if (e < E) {
            int s = ei[e], d = ei[E + e];
            f = (unsigned char)((g_map[s] >= 0 && g_map[d] >= 0) ? 1 : 0);
            out_pe[e] = f ? 1.0f : 0.0f;
        }
        sf[i] = f;
    }
    __syncthreads();
    int t = threadIdx.x;
    int loc[16];
    int s = 0;
#pragma unroll
    for (int j = 0; j < 16; j++) { loc[j] = s; s += sf[t * 16 + j]; }
    ssum[t] = s;
    __syncthreads();
    for (int off = 1; off < 256; off <<= 1) {
        int v = (t >= off) ? ssum[t - off] : 0;
        __syncthreads();
        ssum[t] += v;
        __syncthreads();
    }
    int texcl = ssum[t] - s;
    int gb = g_eexcl[blockIdx.x];
    for (int j = 0; j < 16; j++) {
        int i = t * 16 + j;
        int e = base + i;
        if (e < E && sf[i]) {
            int r = gb + texcl + loc[j];
            int sN = ei[e], dN = ei[E + e];
            out_ei[r]      = (float)sN;
            out_ei[Ek + r] = (float)dN;
            out_eo[r]      = (float)g_map[sN];
            out_eo[Ek + r] = (float)g_map[dN];
            g_kept[r] = e;
        }
    }
}

// ---------------- edge_attr gather: float4 per thread (32 floats = 8 x float4/row) ----------------
__global__ void k_attr(const float* __restrict__ ea, float* __restrict__ outea, int Ek) {
    int tid = blockIdx.x * blockDim.x + threadIdx.x;
    if (tid >= Ek * 8) return;
    int r = tid >> 3, c = tid & 7;
    int e = g_kept[r];
    ((float4*)outea)[tid] = ((const float4*)ea)[e * 8 + c];
}

extern "C" void kernel_launch(void* const* d_in, const int* in_sizes, int n_in,
                              void* d_out, int out_size) {
    const float* x  = (const float*)d_in[0];   // (1, N, 128)
    const float* ea = (const float*)d_in[1];   // (1, E, 32)
    const float* w  = (const float*)d_in[2];   // (1, 128)
    const float* b  = (const float*)d_in[3];   // (1,)
    const int*   ei = (const int*)d_in[4];     // (2, E)

    int N  = in_sizes[0] / 128;
    int E  = in_sizes[4] / 2;
    int NK = N / 2;
    // out_size = NK*128 + 2*Ek + 2*Ek + 32*Ek + NK + E  ->  Ek
    long long Ek_ll = ((long long)out_size - (long long)NK * 129 - (long long)E) / 36;
    int Ek = (int)Ek_ll;

    float* out    = (float*)d_out;
    float* out_x  = out;
    float* out_ei = out_x + (size_t)NK * 128;
    float* out_eo = out_ei + 2 * (size_t)Ek;
    float* out_ea = out_eo + 2 * (size_t)Ek;
    float* out_pi = out_ea + 32 * (size_t)Ek;
    float* out_pe = out_pi + (size_t)NK;

    // 1. scores
    k_scores<<<(N * 32 + 255) / 256, 256>>>(x, w, b, N);

    // 2. exact radix select of rank (NK-1) ascending
    k_zero_hist<<<256, 256>>>();
    k_hist<<<(N + 255) / 256, 256>>>(N, 0);
    k_select<<<1, 256>>>(0, NK - 1);
    k_zero_hist<<<256, 256>>>();
    k_hist<<<(N + 255) / 256, 256>>>(N, 1);
    k_select<<<1, 256>>>(1, 0);

    // 3. stable node compaction -> mapping, pool_idx, pool_indices out
    int nbn = (N + 1023) / 1024;
    k_npart<<<nbn, 256>>>(N);
    k_scan_part<<<1, 32>>>(0, nbn);
    k_nwrite<<<nbn, 256>>>(N, NK, out_pi);

    // 4. new_x gather
    k_xgather<<<(NK * 32 + 255) / 256, 256>>>(x, out_x, NK);

    // 5. edge compaction
    int nbe = (E + 4095) / 4096;
    k_epart<<<nbe, 256>>>(ei, E);
    k_scan_part<<<1, 32>>>(1, nbe);
    k_ewrite<<<nbe, 256>>>(ei, E, Ek, out_ei, out_eo, out_pe);

    // 6. edge_attr gather
    k_attr<<<((size_t)Ek * 8 + 255) / 256, 256>>>(ea, out_ea, Ek);
}

// round 5
// speedup vs baseline: 1.4992x; 1.4992x over previous
#include <cuda_runtime.h>

// Graph TopK pooling: score nodes, exact radix-select threshold, stable
// compaction of kept nodes, gather x, compact edges + attrs.
// All scratch in __device__ globals (no allocs). All kernels graph-capturable.

#define NMAX 100352
#define EMAX 1600000

__device__ float        g_scores[NMAX];
__device__ unsigned int g_hist[65536];
__device__ int          g_prefix;
__device__ int          g_krem;
__device__ unsigned int g_tbits;
__device__ int          g_map[NMAX];
__device__ int          g_poolidx[NMAX / 2 + 256];
__device__ int          g_npart[512];
__device__ int          g_nexcl[512];
__device__ int          g_epart[512];
__device__ int          g_eexcl[512];
__device__ int          g_kept[EMAX];

// ---------------- scores: one warp per node, 128-dim dot ----------------
__global__ void k_scores(const float* __restrict__ x, const float* __restrict__ w,
                         const float* __restrict__ b, int N) {
    int gtid = blockIdx.x * blockDim.x + threadIdx.x;
    int node = gtid >> 5, lane = gtid & 31;
    if (node >= N) return;
    float4 xv = ((const float4*)x)[node * 32 + lane];
    float4 wv = ((const float4*)w)[lane];
    float s = xv.x * wv.x + xv.y * wv.y + xv.z * wv.z + xv.w * wv.w;
#pragma unroll
    for (int o = 16; o > 0; o >>= 1) s += __shfl_down_sync(0xffffffffu, s, o);
    if (lane == 0) {
        float z = s + b[0];
        float sc;
        if (z >= 0.f) sc = 1.f / (1.f + expf(-z));
        else { float e = expf(z); sc = e / (1.f + e); }
        g_scores[node] = sc;
    }
}

__global__ void k_zero_hist() { g_hist[blockIdx.x * 256 + threadIdx.x] = 0u; }

// phase 0: histogram of high 16 bits; phase 1: low 16 bits of elements matching prefix
__global__ void k_hist(int N, int phase) {
    int n = blockIdx.x * blockDim.x + threadIdx.x;
    if (n >= N) return;
    unsigned int bits = __float_as_uint(g_scores[n]);  // scores > 0: bits order = value order
    if (phase == 0) {
        atomicAdd(&g_hist[bits >> 16], 1u);
    } else {
        if ((int)(bits >> 16) == g_prefix) atomicAdd(&g_hist[bits & 0xffffu], 1u);
    }
}

// find bin containing rank k (ascending). 256 threads, thread t owns bins
// [t*256, (t+1)*256) as 64 uint4 independent loads; chunk sums (16 bins each)
// cached in smem so the winning thread resolves the bin with at most one more
// round of 4 independent loads (no serial global walk).
__global__ void k_select(int phase, int k0) {
    __shared__ int s_chunk[256][16];
    __shared__ int s_tot[256];
    int t = threadIdx.x;
    const uint4* __restrict__ h4 = (const uint4*)g_hist;  // 16384 uint4
    int tot = 0;
#pragma unroll
    for (int c = 0; c < 16; c++) {
        int cs = 0;
#pragma unroll
        for (int j = 0; j < 4; j++) {
            uint4 q = h4[t * 64 + c * 4 + j];
            cs += (int)(q.x + q.y + q.z + q.w);
        }
        s_chunk[t][c] = cs;
        tot += cs;
    }
    s_tot[t] = tot;
    __syncthreads();
    for (int off = 1; off < 256; off <<= 1) {
        int v = (t >= off) ? s_tot[t - off] : 0;
        __syncthreads();
        s_tot[t] += v;
        __syncthreads();
    }
    int excl = s_tot[t] - tot;
    int k = (phase == 0) ? k0 : g_krem;
    if (k >= excl && k < excl + tot) {
        int rem = k - excl;
        // find chunk (smem, ALU only)
        int cidx = -1;
#pragma unroll
        for (int c = 0; c < 16; c++) {
            int cs = s_chunk[t][c];
            if (cidx < 0) { if (rem < cs) cidx = c; else rem -= cs; }
        }
        // reload that chunk's 16 bins (4 independent uint4 loads)
        unsigned int bins[16];
#pragma unroll
        for (int j = 0; j < 4; j++) {
            uint4 q = h4[t * 64 + cidx * 4 + j];
            bins[j * 4 + 0] = q.x; bins[j * 4 + 1] = q.y;
            bins[j * 4 + 2] = q.z; bins[j * 4 + 3] = q.w;
        }
        int bidx = -1;
#pragma unroll
        for (int bb = 0; bb < 16; bb++) {
            int cnt = (int)bins[bb];
            if (bidx < 0) { if (rem < cnt) bidx = bb; else rem -= cnt; }
        }
        int bin = t * 256 + cidx * 16 + bidx;
        if (phase == 0) { g_prefix = bin; g_krem = rem; }
        else            { g_tbits = ((unsigned)g_prefix << 16) | (unsigned)bin; }
    }
}

// ---------------- node compaction: count / scan / write ----------------
__global__ void k_npart(int N) {
    __shared__ int red[256];
    int base = blockIdx.x * 1024;
    unsigned int tb = g_tbits;
    int c = 0;
    for (int i = threadIdx.x; i < 1024; i += 256) {
        int n = base + i;
        if (n < N) c += (__float_as_uint(g_scores[n]) >= tb) ? 1 : 0;
    }
    red[threadIdx.x] = c;
    __syncthreads();
    for (int off = 128; off > 0; off >>= 1) {
        if (threadIdx.x < off) red[threadIdx.x] += red[threadIdx.x + off];
        __syncthreads();
    }
    if (threadIdx.x == 0) g_npart[blockIdx.x] = red[0];
}

// parallel exclusive scan of partition counts (nb <= 512), replaces the
// single-thread serial-load scan.
__global__ void k_scan_part(int which, int nb) {
    __shared__ int s[512];
    int t = threadIdx.x;
    int v = 0;
    if (t < nb) v = (which == 0) ? g_npart[t] : g_epart[t];
    s[t] = v;
    __syncthreads();
    for (int off = 1; off < 512; off <<= 1) {
        int u = (t >= off) ? s[t - off] : 0;
        __syncthreads();
        s[t] += u;
        __syncthreads();
    }
    if (t < nb) {
        int excl = s[t] - v;
        if (which == 0) g_nexcl[t] = excl; else g_eexcl[t] = excl;
    }
}

__global__ void k_nwrite(int N, int NK, float* __restrict__ out_pool) {
    __shared__ unsigned char sf[1024];
    __shared__ int ssum[256];
    int base = blockIdx.x * 1024;
    unsigned int tb = g_tbits;
    for (int i = threadIdx.x; i < 1024; i += 256) {
        int n = base + i;
        sf[i] = (n < N) ? (unsigned char)(__float_as_uint(g_scores[n]) >= tb) : (unsigned char)0;
    }
    __syncthreads();
    int t = threadIdx.x;
    int loc[4];
    int s = 0;
#pragma unroll
    for (int j = 0; j < 4; j++) { loc[j] = s; s += sf[t * 4 + j]; }
    ssum[t] = s;
    __syncthreads();
    for (int off = 1; off < 256; off <<= 1) {
        int v = (t >= off) ? ssum[t - off] : 0;
        __syncthreads();
        ssum[t] += v;
        __syncthreads();
    }
    int texcl = ssum[t] - s;
    int gb = g_nexcl[blockIdx.x];
#pragma unroll
    for (int j = 0; j < 4; j++) {
        int n = base + t * 4 + j;
        if (n >= N) continue;
        int m = -1;
        if (sf[t * 4 + j]) {
            int r = gb + texcl + loc[j];
            if (r < NK) {  // stable truncation: first NK masked nodes by index
                m = r;
                g_poolidx[r] = n;
                out_pool[r] = (float)n;
            }
        }
        g_map[n] = m;
    }
}

// ---------------- new_x gather: float4 per thread ----------------
__global__ void k_xgather(const float* __restrict__ x, float* __restrict__ outx, int NK) {
    int tid = blockIdx.x * blockDim.x + threadIdx.x;
    if (tid >= NK * 32) return;
    int r = tid >> 5, c = tid & 31;
    int n = g_poolidx[r];
    ((float4*)outx)[tid] = ((const float4*)x)[n * 32 + c];
}

// ---------------- edge compaction: count / scan / write ----------------
__global__ void k_epart(const int* __restrict__ ei, int E) {
    __shared__ int red[256];
    int base = blockIdx.x * 4096;
    int c = 0;
    for (int i = threadIdx.x; i < 4096; i += 256) {
        int e = base + i;
        if (e < E) {
            int s = ei[e], d = ei[E + e];
            c += (g_map[s] >= 0 && g_map[d] >= 0) ? 1 : 0;
        }
    }
    red[threadIdx.x] = c;
    __syncthreads();
    for (int off = 128; off > 0; off >>= 1) {
        if (threadIdx.x < off) red[threadIdx.x] += red[threadIdx.x + off];
        __syncthreads();
    }
    if (threadIdx.x == 0) g_epart[blockIdx.x] = red[0];
}

__global__ void k_ewrite(const int* __restrict__ ei, int E, int Ek,
                         float* __restrict__ out_ei, float* __restrict__ out_eo,
                         float* __restrict__ out_pe) {
    __shared__ unsigned char sf[4096];
    __shared__ int ssum[256];
    int base = blockIdx.x * 4096;
    for (int i = threadIdx.x; i < 4096; i += 256) {
        int e = base + i;
        unsigned char f = 0;
        if (e < E) {
            int s = ei[e], d = ei[E + e];
            f = (unsigned char)((g_map[s] >= 0 && g_map[d] >= 0) ? 1 : 0);
            out_pe[e] = f ? 1.0f : 0.0f;
        }
        sf[i] = f;
    }
    __syncthreads();
    int t = threadIdx.x;
    int loc[16];
    int s = 0;
#pragma unroll
    for (int j = 0; j < 16; j++) { loc[j] = s; s += sf[t * 16 + j]; }
    ssum[t] = s;
    __syncthreads();
    for (int off = 1; off < 256; off <<= 1) {
        int v = (t >= off) ? ssum[t - off] : 0;
        __syncthreads();
        ssum[t] += v;
        __syncthreads();
    }
    int texcl = ssum[t] - s;
    int gb = g_eexcl[blockIdx.x];
    for (int j = 0; j < 16; j++) {
        int i = t * 16 + j;
        int e = base + i;
        if (e < E && sf[i]) {
            int r = gb + texcl + loc[j];
            int sN = ei[e], dN = ei[E + e];
            out_ei[r]      = (float)sN;
            out_ei[Ek + r] = (float)dN;
            out_eo[r]      = (float)g_map[sN];
            out_eo[Ek + r] = (float)g_map[dN];
            g_kept[r] = e;
        }
    }
}

// ---------------- edge_attr gather: float4 per thread (32 floats = 8 x float4/row) ----------------
__global__ void k_attr(const float* __restrict__ ea, float* __restrict__ outea, int Ek) {
    int tid = blockIdx.x * blockDim.x + threadIdx.x;
    if (tid >= Ek * 8) return;
    int r = tid >> 3, c = tid & 7;
    int e = g_kept[r];
    ((float4*)outea)[tid] = ((const float4*)ea)[e * 8 + c];
}

extern "C" void kernel_launch(void* const* d_in, const int* in_sizes, int n_in,
                              void* d_out, int out_size) {
    const float* x  = (const float*)d_in[0];   // (1, N, 128)
    const float* ea = (const float*)d_in[1];   // (1, E, 32)
    const float* w  = (const float*)d_in[2];   // (1, 128)
    const float* b  = (const float*)d_in[3];   // (1,)
    const int*   ei = (const int*)d_in[4];     // (2, E)

    int N  = in_sizes[0] / 128;
    int E  = in_sizes[4] / 2;
    int NK = N / 2;
    // out_size = NK*128 + 2*Ek + 2*Ek + 32*Ek + NK + E  ->  Ek
    long long Ek_ll = ((long long)out_size - (long long)NK * 129 - (long long)E) / 36;
    int Ek = (int)Ek_ll;

    float* out    = (float*)d_out;
    float* out_x  = out;
    float* out_ei = out_x + (size_t)NK * 128;
    float* out_eo = out_ei + 2 * (size_t)Ek;
    float* out_ea = out_eo + 2 * (size_t)Ek;
    float* out_pi = out_ea + 32 * (size_t)Ek;
    float* out_pe = out_pi + (size_t)NK;

    // 1. scores
    k_scores<<<(N * 32 + 255) / 256, 256>>>(x, w, b, N);

    // 2. exact radix select of rank (NK-1) ascending
    k_zero_hist<<<256, 256>>>();
    k_hist<<<(N + 255) / 256, 256>>>(N, 0);
    k_select<<<1, 256>>>(0, NK - 1);
    k_zero_hist<<<256, 256>>>();
    k_hist<<<(N + 255) / 256, 256>>>(N, 1);
    k_select<<<1, 256>>>(1, 0);

    // 3. stable node compaction -> mapping, pool_idx, pool_indices out
    int nbn = (N + 1023) / 1024;
    k_npart<<<nbn, 256>>>(N);
    k_scan_part<<<1, 512>>>(0, nbn);
    k_nwrite<<<nbn, 256>>>(N, NK, out_pi);

    // 4. new_x gather
    k_xgather<<<(NK * 32 + 255) / 256, 256>>>(x, out_x, NK);

    // 5. edge compaction
    int nbe = (E + 4095) / 4096;
    k_epart<<<nbe, 256>>>(ei, E);
    k_scan_part<<<1, 512>>>(1, nbe);
    k_ewrite<<<nbe, 256>>>(ei, E, Ek, out_ei, out_eo, out_pe);

    // 6. edge_attr gather
    k_attr<<<((size_t)Ek * 8 + 255) / 256, 256>>>(ea, out_ea, Ek);
}

// round 7
// speedup vs baseline: 1.7598x; 1.1738x over previous
#include <cuda_runtime.h>

// Graph TopK pooling — R5: coarse-histogram radix select (tiny k_select),
// decoupled-lookback single-pass node & edge compaction, fused scratch zeroing.
// All scratch in __device__ globals. All kernels graph-capturable.

#define NMAX 100352
#define EMAX 1600000

__device__ float        g_scores[NMAX];
__device__ unsigned int g_hist1[65536];
__device__ unsigned int g_hist2[65536];
__device__ unsigned int g_c1[256];
__device__ unsigned int g_c2[256];
__device__ int          g_prefix;
__device__ int          g_krem;
__device__ unsigned int g_tbits;
__device__ int          g_map[NMAX];
__device__ int          g_poolidx[NMAX / 2 + 256];
__device__ int          g_kept[EMAX];
__device__ unsigned int g_ntile[256];   // packed flag<<30 | value
__device__ unsigned int g_etile[512];

// ---------------- scores (one warp per node) + fused scratch zeroing ----------------
__global__ void k_scores(const float* __restrict__ x, const float* __restrict__ w,
                         const float* __restrict__ b, int N) {
    int bidx = blockIdx.x, t = threadIdx.x;
    // fused zeroing of all per-replay scratch
    if (bidx < 256) {
        g_hist1[bidx * 256 + t] = 0u;
        g_hist2[bidx * 256 + t] = 0u;
    } else if (bidx == 256) {
        g_c1[t] = 0u; g_c2[t] = 0u;
    } else if (bidx == 257) {
        g_etile[t] = 0u; g_etile[256 + t] = 0u;
    } else if (bidx == 258) {
        g_ntile[t] = 0u;
    }
    int gtid = bidx * blockDim.x + t;
    int node = gtid >> 5, lane = gtid & 31;
    if (node >= N) return;
    float4 xv = ((const float4*)x)[node * 32 + lane];
    float4 wv = ((const float4*)w)[lane];
    float s = xv.x * wv.x + xv.y * wv.y + xv.z * wv.z + xv.w * wv.w;
#pragma unroll
    for (int o = 16; o > 0; o >>= 1) s += __shfl_down_sync(0xffffffffu, s, o);
    if (lane == 0) {
        float z = s + b[0];
        float sc;
        if (z >= 0.f) sc = 1.f / (1.f + expf(-z));
        else { float e = expf(z); sc = e / (1.f + e); }
        g_scores[node] = sc;
    }
}

// ---------------- histograms (fine 256-way-within-bucket + coarse 256) ----------------
// phase 0: hi16 -> hist1, hi8 -> c1.  phase 1 (bits matching prefix): lo16 -> hist2, mid8 -> c2.
__global__ void k_hist(int N, int phase) {
    int i = blockIdx.x * blockDim.x + threadIdx.x;
    int n4 = (N + 3) >> 2;
    if (i >= n4) return;
    float4 sv = ((const float4*)g_scores)[i];
    unsigned int bs[4] = { __float_as_uint(sv.x), __float_as_uint(sv.y),
                           __float_as_uint(sv.z), __float_as_uint(sv.w) };
    int pfx = g_prefix;
#pragma unroll
    for (int j = 0; j < 4; j++) {
        int n = 4 * i + j;
        if (n >= N) break;
        unsigned int bits = bs[j];  // scores > 0: uint order == float order
        if (phase == 0) {
            atomicAdd(&g_hist1[bits >> 16], 1u);
            atomicAdd(&g_c1[bits >> 24], 1u);
        } else if ((int)(bits >> 16) == pfx) {
            atomicAdd(&g_hist2[bits & 0xffffu], 1u);
            atomicAdd(&g_c2[(bits >> 8) & 0xffu], 1u);
        }
    }
}

// find bin containing rank k (ascending): scan 256 coarse, then 256 fine bins
// of the single winning bucket. Total global reads ~1.3 KB.
__global__ void k_select(int phase, int k0) {
    __shared__ int sc[256];
    __shared__ int sf2[64];
    __shared__ int s_bucket, s_rem;
    int t = threadIdx.x;
    const unsigned int* __restrict__ C = (phase == 0) ? g_c1 : g_c2;
    const unsigned int* __restrict__ H = (phase == 0) ? g_hist1 : g_hist2;
    int v = (int)C[t];
    sc[t] = v;
    __syncthreads();
    for (int off = 1; off < 256; off <<= 1) {
        int u = (t >= off) ? sc[t - off] : 0;
        __syncthreads();
        sc[t] += u;
        __syncthreads();
    }
    int k = (phase == 0) ? k0 : g_krem;
    int excl = sc[t] - v;
    if (k >= excl && k < excl + v) { s_bucket = t; s_rem = k - excl; }
    __syncthreads();
    int wb = s_bucket;
    uint4 q = make_uint4(0, 0, 0, 0);
    int fv = 0;
    if (t < 64) {
        q = ((const uint4*)H)[wb * 64 + t];
        fv = (int)(q.x + q.y + q.z + q.w);
        sf2[t] = fv;
    }
    __syncthreads();
    for (int off = 1; off < 64; off <<= 1) {
        int u = (t >= off && t < 64) ? sf2[t - off] : 0;
        __syncthreads();
        if (t < 64) sf2[t] += u;
        __syncthreads();
    }
    if (t < 64) {
        int e2 = sf2[t] - fv;
        int rem = s_rem;
        if (rem >= e2 && rem < e2 + fv) {
            int r = rem - e2;
            int bin;
            if (r < (int)q.x)                       { bin = wb * 256 + t * 4 + 0; }
            else { r -= (int)q.x; if (r < (int)q.y) { bin = wb * 256 + t * 4 + 1; }
            else { r -= (int)q.y; if (r < (int)q.z) { bin = wb * 256 + t * 4 + 2; }
            else { r -= (int)q.z;                     bin = wb * 256 + t * 4 + 3; } } }
            if (phase == 0) { g_prefix = bin; g_krem = r; }
            else            { g_tbits = ((unsigned)g_prefix << 16) | (unsigned)bin; }
        }
    }
}

// ---------------- warp-parallel decoupled lookback (warp 0 of each block) ----------------
__device__ __forceinline__ int lookback_excl(unsigned int* tiles, int bid, int cnt, int t) {
    // Returns exclusive prefix (valid in all lanes of warp 0 only via lane 0 -> caller smem).
    if (t == 0) {
        unsigned int word = (((bid == 0) ? 2u : 1u) << 30) | (unsigned)cnt;
        atomicExch(&tiles[bid], word);
    }
    __syncwarp();
    int excl = 0;
    if (bid > 0) {
        int p = bid - 1;
        bool done = false;
        while (!done) {
            int idx = p - t;
            unsigned int v = 0;
            if (idx >= 0) {
                do { v = *((volatile unsigned int*)&tiles[idx]); } while ((v >> 30) == 0u);
            }
            unsigned int fl = (idx >= 0) ? (v >> 30) : 0u;
            unsigned int pm = __ballot_sync(0xffffffffu, fl == 2u);
            int stop_lane = (pm != 0u) ? (__ffs(pm) - 1) : 32;
            int val = (idx >= 0 && t <= stop_lane) ? (int)(v & 0x3fffffffu) : 0;
#pragma unroll
            for (int o = 16; o > 0; o >>= 1) val += __shfl_down_sync(0xffffffffu, val, o);
            if (t == 0) excl += val;
            done = (pm != 0u) || (p - 31 < 0);
            p -= 32;
        }
        if (t == 0) atomicExch(&tiles[bid], (2u << 30) | (unsigned)(excl + cnt));
    }
    return excl;  // meaningful on lane 0
}

// ---------------- single-pass node compaction (mask, scan, map, poolidx, out_pi) ----------------
__global__ void k_nodes(int N, int NK, float* __restrict__ out_pool) {
    __shared__ unsigned char sf[1024];
    __shared__ int ssum[256];
    __shared__ int s_gb;
    int bid = blockIdx.x, t = threadIdx.x;
    int base = bid * 1024;
    unsigned int tb = g_tbits;
    for (int i = t; i < 1024; i += 256) {
        int n = base + i;
        sf[i] = (n < N) ? (unsigned char)(__float_as_uint(g_scores[n]) >= tb) : (unsigned char)0;
    }
    __syncthreads();
    int loc[4];
    int s = 0;
#pragma unroll
    for (int j = 0; j < 4; j++) { loc[j] = s; s += sf[t * 4 + j]; }
    ssum[t] = s;
    __syncthreads();
    for (int off = 1; off < 256; off <<= 1) {
        int u = (t >= off) ? ssum[t - off] : 0;
        __syncthreads();
        ssum[t] += u;
        __syncthreads();
    }
    int cnt = ssum[255];
    if (t < 32) {
        int excl = lookback_excl(g_ntile, bid, cnt, t);
        if (t == 0) s_gb = excl;
    }
    __syncthreads();
    int texcl = ssum[t] - s;
    int gb = s_gb;
#pragma unroll
    for (int j = 0; j < 4; j++) {
        int n = base + t * 4 + j;
        if (n >= N) continue;
        int m = -1;
        if (sf[t * 4 + j]) {
            int r = gb + texcl + loc[j];
            if (r < NK) {  // stable truncation: first NK masked nodes by index
                m = r;
                g_poolidx[r] = n;
                out_pool[r] = (float)n;
            }
        }
        g_map[n] = m;
    }
}

// ---------------- new_x gather: float4 per thread ----------------
__global__ void k_xgather(const float* __restrict__ x, float* __restrict__ outx, int NK) {
    int tid = blockIdx.x * blockDim.x + threadIdx.x;
    if (tid >= NK * 32) return;
    int r = tid >> 5, c = tid & 31;
    int n = g_poolidx[r];
    ((float4*)outx)[tid] = ((const float4*)x)[n * 32 + c];
}

// ---------------- single-pass edge compaction (flags, pe, scan, compact, kept) ----------------
__global__ void k_edges(const int* __restrict__ ei, int E, int Ek,
                        float* __restrict__ out_ei, float* __restrict__ out_eo,
                        float* __restrict__ out_pe) {
    __shared__ int s_src[4096];
    __shared__ int s_dst[4096];
    __shared__ unsigned char sf[4096];
    __shared__ int ssum[256];
    __shared__ int s_gb;
    int bid = blockIdx.x, t = threadIdx.x;
    int base = bid * 4096;
    for (int i = t; i < 4096; i += 256) {
        int e = base + i;
        unsigned char f = 0;
        if (e < E) {
            int sN = ei[e], dN = ei[E + e];
            s_src[i] = sN; s_dst[i] = dN;
            f = (unsigned char)((g_map[sN] >= 0 && g_map[dN] >= 0) ? 1 : 0);
            out_pe[e] = f ? 1.0f : 0.0f;
        }
        sf[i] = f;
    }
    __syncthreads();
    int loc[16];
    int s = 0;
#pragma unroll
    for (int j = 0; j < 16; j++) { loc[j] = s; s += sf[t * 16 + j]; }
    ssum[t] = s;
    __syncthreads();
    for (int off = 1; off < 256; off <<= 1) {
        int u = (t >= off) ? ssum[t - off] : 0;
        __syncthreads();
        ssum[t] += u;
        __syncthreads();
    }
    int cnt = ssum[255];
    if (t < 32) {
        int excl = lookback_excl(g_etile, bid, cnt, t);
        if (t == 0) s_gb = excl;
    }
    __syncthreads();
    int texcl = ssum[t] - s;
    int gb = s_gb;
    for (int j = 0; j < 16; j++) {
        int i = t * 16 + j;
        int e = base + i;
        if (e < E && sf[i]) {
            int r = gb + texcl + loc[j];
            int sN = s_src[i], dN = s_dst[i];
            out_ei[r]      = (float)sN;
            out_ei[Ek + r] = (float)dN;
            out_eo[r]      = (float)g_map[sN];
            out_eo[Ek + r] = (float)g_map[dN];
            g_kept[r] = e;
        }
    }
}

// ---------------- edge_attr gather: float4 per thread ----------------
__global__ void k_attr(const float* __restrict__ ea, float* __restrict__ outea, int Ek) {
    int tid = blockIdx.x * blockDim.x + threadIdx.x;
    if (tid >= Ek * 8) return;
    int r = tid >> 3, c = tid & 7;
    int e = g_kept[r];
    ((float4*)outea)[tid] = ((const float4*)ea)[e * 8 + c];
}

extern "C" void kernel_launch(void* const* d_in, const int* in_sizes, int n_in,
                              void* d_out, int out_size) {
    const float* x  = (const float*)d_in[0];   // (1, N, 128)
    const float* ea = (const float*)d_in[1];   // (1, E, 32)
    const float* w  = (const float*)d_in[2];   // (1, 128)
    const float* b  = (const float*)d_in[3];   // (1,)
    const int*   ei = (const int*)d_in[4];     // (2, E)

    int N  = in_sizes[0] / 128;
    int E  = in_sizes[4] / 2;
    int NK = N / 2;
    long long Ek_ll = ((long long)out_size - (long long)NK * 129 - (long long)E) / 36;
    int Ek = (int)Ek_ll;

    float* out    = (float*)d_out;
    float* out_x  = out;
    float* out_ei = out_x + (size_t)NK * 128;
    float* out_eo = out_ei + 2 * (size_t)Ek;
    float* out_ea = out_eo + 2 * (size_t)Ek;
    float* out_pi = out_ea + 32 * (size_t)Ek;
    float* out_pe = out_pi + (size_t)NK;

    // 1. scores + zero all scratch
    k_scores<<<(N * 32 + 255) / 256, 256>>>(x, w, b, N);

    // 2. exact radix select of rank (NK-1) ascending (coarse+fine histograms)
    int nh = ((N + 3) / 4 + 255) / 256;
    k_hist<<<nh, 256>>>(N, 0);
    k_select<<<1, 256>>>(0, NK - 1);
    k_hist<<<nh, 256>>>(N, 1);
    k_select<<<1, 256>>>(1, 0);

    // 3. single-pass node compaction
    int nbn = (N + 1023) / 1024;
    k_nodes<<<nbn, 256>>>(N, NK, out_pi);

    // 4. new_x gather
    k_xgather<<<(NK * 32 + 255) / 256, 256>>>(x, out_x, NK);

    // 5. single-pass edge compaction
    int nbe = (E + 4095) / 4096;
    k_edges<<<nbe, 256>>>(ei, E, Ek, out_ei, out_eo, out_pe);

    // 6. edge_attr gather
    k_attr<<<((size_t)Ek * 8 + 255) / 256, 256>>>(ea, out_ea, Ek);
}